// round 2
// baseline (speedup 1.0000x reference)
#include <cuda_runtime.h>

// Problem constants
#define BB 4
#define NN 4096
#define DD 1024
#define L  32                 // timesteps per chunk
#define C  (NN / L)           // 128 chunks per row
#define DT 256                // threads per block = d-tile width
#define NCOL (BB * (DD / DT)) // 16 independent chains
#define NBLK (C * NCOL)       // 2048 blocks

// Scratch (static __device__ globals: allowed; no runtime allocation)
__device__ float2 g_agg [NBLK * DT];
__device__ float2 g_incl[NBLK * DT];
__device__ int    g_flags[NBLK];     // 0 = empty, 1 = aggregate ready, 2 = inclusive ready

__global__ __launch_bounds__(DT)
void assoc_scan_kernel(const float* __restrict__ gates,
                       const float* __restrict__ inputs,
                       float* __restrict__ out)
{
    const int bx    = blockIdx.x;
    const int chunk = bx >> 4;        // slow-varying -> earlier chunks scheduled first
    const int col   = bx & 15;        // chain id: (b, d-tile)
    const int b     = col >> 2;
    const int dt    = col & 3;
    const int tid   = threadIdx.x;
    const int d     = dt * DT + tid;

    const long base = ((long)b * NN + (long)chunk * L) * (long)DD + d;

    // ---- Load chunk into registers (fully unrolled -> high MLP, coalesced) ----
    float gv[L], xv[L];
#pragma unroll
    for (int t = 0; t < L; t++) {
        gv[t] = __ldg(gates  + base + (long)t * DD);
        xv[t] = __ldg(inputs + base + (long)t * DD);
    }

    // ---- Local chunk aggregate: (A = prod g, S = scan value with h_in = 0) ----
    float A = 1.0f, S = 0.0f;
#pragma unroll
    for (int t = 0; t < L; t++) {
        S = fmaf(gv[t], S, xv[t]);
        A = A * gv[t];
    }

    const int slot = bx * DT + tid;
    float accA = 1.0f, accS = 0.0f;   // exclusive prefix (carry) for this chunk

    if (chunk == 0) {
        // Publish inclusive prefix directly.
        float2 v; v.x = A; v.y = S;
        __stcg(&g_incl[slot], v);
        __threadfence();
        __syncthreads();
        if (tid == 0) atomicExch(&g_flags[bx], 2);
    } else {
        // Publish aggregate ASAP so successors can make progress.
        float2 v; v.x = A; v.y = S;
        __stcg(&g_agg[slot], v);
        __threadfence();
        __syncthreads();
        if (tid == 0) atomicExch(&g_flags[bx], 1);

        // ---- Decoupled lookback ----
        __shared__ int s_flag;
        int k = chunk - 1;
        for (;;) {
            if (tid == 0) {
                int f;
                do { f = atomicAdd(&g_flags[k * 16 + col], 0); } while (f == 0);
                s_flag = f;
            }
            __syncthreads();
            const int f = s_flag;
            const float2* src = (f == 2) ? g_incl : g_agg;
            float2 p = __ldcg(&src[(k * 16 + col) * DT + tid]);
            // combine(pred, acc): acc is the later (suffix) segment
            accS = fmaf(accA, p.y, accS);
            accA = accA * p.x;
            __syncthreads();          // protect s_flag reuse
            if (f == 2) break;
            k--;
        }

        // Publish our inclusive prefix: combine(prefix, local)
        float2 inc;
        inc.x = A * accA;
        inc.y = fmaf(A, accS, S);
        __stcg(&g_incl[slot], inc);
        __threadfence();
        __syncthreads();
        if (tid == 0) atomicExch(&g_flags[bx], 2);
    }

    // ---- Recompute outputs from registers with the carry-in ----
    float h = accS;
#pragma unroll
    for (int t = 0; t < L; t++) {
        h = fmaf(gv[t], h, xv[t]);
        out[base + (long)t * DD] = h;
    }
}

extern "C" void kernel_launch(void* const* d_in, const int* in_sizes, int n_in,
                              void* d_out, int out_size)
{
    const float* gates  = (const float*)d_in[0];
    const float* inputs = (const float*)d_in[1];
    float*       out    = (float*)d_out;

    void* flags_ptr = nullptr;
    cudaGetSymbolAddress(&flags_ptr, g_flags);
    cudaMemsetAsync(flags_ptr, 0, NBLK * sizeof(int));   // reset chain state (captured node)

    assoc_scan_kernel<<<NBLK, DT>>>(gates, inputs, out);
}